// round 1
// baseline (speedup 1.0000x reference)
#include <cuda_runtime.h>
#include <cuda_bf16.h>
#include <cstdint>

// Problem constants
#define NB   16
#define NT   4096
#define NTOK (NB * NT)      // 65536 tokens
#define DIM  128
#define KC   1024           // codebook size
#define BETA 0.25f

// Tiling
#define TM 128              // tokens per CTA
#define TK 128              // codes per K-chunk
#define NCHUNK (KC / TK)    // 8
#define PITCH 132           // smem row pitch in floats (132*4=528 B, 16B aligned)
#define NTHREADS 256

// Output layout (float32, reference return order)
#define OFF_ZQ   0
#define SZ_ZQ    (NTOK * DIM)                 // 8388608
#define OFF_SIM  (OFF_ZQ + SZ_ZQ)             // 8388608
#define SZ_SIM   ((size_t)NTOK * KC)          // 67108864
#define OFF_IDS  (OFF_SIM + SZ_SIM)           // 75497472
#define SZ_IDS   NTOK
#define OFF_LOSS (OFF_IDS + SZ_IDS)           // 75563008

// Device scratch (no allocations allowed)
__device__ float g_nsqE[KC];
__device__ float g_rnE[KC];
__device__ float g_partial[NTOK / TM];        // 512 per-CTA loss partials

// ---------------------------------------------------------------------------
// Kernel 1: codebook norms
// ---------------------------------------------------------------------------
__global__ void vq_norms_kernel(const float* __restrict__ E) {
    int k = blockIdx.x * blockDim.x + threadIdx.x;   // grid 8 x 128
    const float4* row = reinterpret_cast<const float4*>(E + (size_t)k * DIM);
    float s = 0.f;
#pragma unroll
    for (int i = 0; i < DIM / 4; i++) {
        float4 v = row[i];
        s = fmaf(v.x, v.x, s);
        s = fmaf(v.y, v.y, s);
        s = fmaf(v.z, v.z, s);
        s = fmaf(v.w, v.w, s);
    }
    g_nsqE[k] = s;
    g_rnE[k]  = rsqrtf(s);
}

// ---------------------------------------------------------------------------
// Kernel 2: fused GEMM + similarity + argmin + z_q gather + loss partial
//   CTA: 128 tokens x all 1024 codes (8 chunks of 128)
//   thread (tx,ty) in 16x16; 8x8 register tile using split-half indexing:
//   tokens {ty*4+i, 64+ty*4+i}, codes {tx*4+j, 64+tx*4+j}
// ---------------------------------------------------------------------------
__global__ __launch_bounds__(NTHREADS, 1)
void vq_main_kernel(const float* __restrict__ z,
                    const float* __restrict__ E,
                    float* __restrict__ zq,
                    float* __restrict__ sim,
                    float* __restrict__ ids_out) {
    extern __shared__ float sm[];
    float* zT    = sm;                       // [DIM][PITCH]
    float* eT    = zT + DIM * PITCH;         // [DIM][PITCH]
    float* s_nz  = eT + DIM * PITCH;         // [TM]
    float* s_rnz = s_nz + TM;                // [TM]
    float* s_ne  = s_rnz + TM;               // [TK]
    float* s_rne = s_ne + TK;                // [TK]
    float* s_red = s_rne + TK;               // [NTHREADS]
    int*   s_ids = reinterpret_cast<int*>(s_red + NTHREADS); // [TM]

    const int tid = threadIdx.x;
    const int tx  = tid & 15;
    const int ty  = tid >> 4;
    const int base = blockIdx.x * TM;

    // ---- load z tile (coalesced) transposed into smem ----
#pragma unroll
    for (int it = 0; it < (TM * DIM / 4) / NTHREADS; it++) {
        int f   = tid + it * NTHREADS;           // 0..4095
        int tok = f >> 5;
        int d4  = (f & 31) << 2;
        float4 v = *reinterpret_cast<const float4*>(z + (size_t)(base + tok) * DIM + d4);
        zT[(d4 + 0) * PITCH + tok] = v.x;
        zT[(d4 + 1) * PITCH + tok] = v.y;
        zT[(d4 + 2) * PITCH + tok] = v.z;
        zT[(d4 + 3) * PITCH + tok] = v.w;
    }
    __syncthreads();

    // ---- per-token squared norms ----
    if (tid < TM) {
        float s = 0.f;
#pragma unroll 8
        for (int d = 0; d < DIM; d++) {
            float v = zT[d * PITCH + tid];
            s = fmaf(v, v, s);
        }
        s_nz[tid]  = s;
        s_rnz[tid] = rsqrtf(s);
    }

    // running argmin over dist' = ne - 2*dot (nz is per-token constant)
    float bd[8];
    int   bi[8];
#pragma unroll
    for (int i = 0; i < 8; i++) { bd[i] = 3.4e38f; bi[i] = 0; }

    for (int kc = 0; kc < NCHUNK; kc++) {
        const int kbase = kc * TK;
        __syncthreads();   // protect eT (reused buffer) + first-iter covers s_nz

        // load E chunk transposed
#pragma unroll
        for (int it = 0; it < (TK * DIM / 4) / NTHREADS; it++) {
            int f  = tid + it * NTHREADS;
            int kk = f >> 5;
            int d4 = (f & 31) << 2;
            float4 v = *reinterpret_cast<const float4*>(E + (size_t)(kbase + kk) * DIM + d4);
            eT[(d4 + 0) * PITCH + kk] = v.x;
            eT[(d4 + 1) * PITCH + kk] = v.y;
            eT[(d4 + 2) * PITCH + kk] = v.z;
            eT[(d4 + 3) * PITCH + kk] = v.w;
        }
        if (tid < TK) {
            s_ne[tid]  = g_nsqE[kbase + tid];
            s_rne[tid] = g_rnE[kbase + tid];
        }
        __syncthreads();

        // ---- 8x8 register-tile GEMM over d ----
        float acc[8][8];
#pragma unroll
        for (int i = 0; i < 8; i++)
#pragma unroll
            for (int j = 0; j < 8; j++) acc[i][j] = 0.f;

#pragma unroll 4
        for (int d = 0; d < DIM; d++) {
            const float* zr = zT + d * PITCH;
            const float* er = eT + d * PITCH;
            float4 zA = *reinterpret_cast<const float4*>(zr + ty * 4);
            float4 zB = *reinterpret_cast<const float4*>(zr + 64 + ty * 4);
            float4 eA = *reinterpret_cast<const float4*>(er + tx * 4);
            float4 eB = *reinterpret_cast<const float4*>(er + 64 + tx * 4);
            float za[8] = {zA.x, zA.y, zA.z, zA.w, zB.x, zB.y, zB.z, zB.w};
            float eb[8] = {eA.x, eA.y, eA.z, eA.w, eB.x, eB.y, eB.z, eB.w};
#pragma unroll
            for (int i = 0; i < 8; i++)
#pragma unroll
                for (int j = 0; j < 8; j++)
                    acc[i][j] = fmaf(za[i], eb[j], acc[i][j]);
        }

        // ---- epilogue: similarity write + argmin update ----
#pragma unroll
        for (int i = 0; i < 8; i++) {
            const int trow = (i < 4) ? (ty * 4 + i) : (64 + ty * 4 + (i - 4));
            const float rnz = s_rnz[trow];
            float* simrow = sim + (size_t)(base + trow) * KC + kbase;

            float4 sv0, sv1;
            float* sv0p = &sv0.x;
            float* sv1p = &sv1.x;
#pragma unroll
            for (int j = 0; j < 8; j++) {
                const int kcol = (j < 4) ? (tx * 4 + j) : (64 + tx * 4 + (j - 4));
                const float dotv = acc[i][j];
                const float dist = fmaf(-2.f, dotv, s_ne[kcol]);
                if (dist < bd[i]) { bd[i] = dist; bi[i] = kbase + kcol; }
                const float s = dotv * rnz * s_rne[kcol];
                if (j < 4) sv0p[j] = s; else sv1p[j - 4] = s;
            }
            *reinterpret_cast<float4*>(simrow + tx * 4)      = sv0;
            *reinterpret_cast<float4*>(simrow + 64 + tx * 4) = sv1;
        }
    }

    // ---- argmin reduce across the 16 tx threads (width-16 shuffles) ----
    float lsum = 0.f;
#pragma unroll
    for (int i = 0; i < 8; i++) {
        float d = bd[i];
        int   id = bi[i];
#pragma unroll
        for (int off = 8; off; off >>= 1) {
            float od = __shfl_xor_sync(0xffffffffu, d, off, 16);
            int   oi = __shfl_xor_sync(0xffffffffu, id, off, 16);
            if (od < d || (od == d && oi < id)) { d = od; id = oi; }
        }
        if (tx == 0) {
            const int trow = (i < 4) ? (ty * 4 + i) : (64 + ty * 4 + (i - 4));
            s_ids[trow] = id;
            // ||z - e||^2 = nz + ne - 2*dot  (= d + nz), clamp for safety
            lsum += sqrtf(fmaxf(d + s_nz[trow], 0.f));
        }
    }

    // ---- deterministic block loss reduction ----
    s_red[tid] = lsum;
    __syncthreads();
#pragma unroll
    for (int off = NTHREADS / 2; off; off >>= 1) {
        if (tid < off) s_red[tid] += s_red[tid + off];
        __syncthreads();
    }
    if (tid == 0) g_partial[blockIdx.x] = s_red[0];

    // ---- ids output (as float) ----
    if (tid < TM) ids_out[base + tid] = (float)s_ids[tid];

    // ---- cooperative z_q gather (coalesced writes, E is L2-hot) ----
#pragma unroll
    for (int it = 0; it < (TM * DIM / 4) / NTHREADS; it++) {
        int f   = tid + it * NTHREADS;
        int tok = f >> 5;
        int c4  = (f & 31) << 2;
        int id  = s_ids[tok];
        float4 v = *reinterpret_cast<const float4*>(E + (size_t)id * DIM + c4);
        *reinterpret_cast<float4*>(zq + (size_t)(base + tok) * DIM + c4) = v;
    }
}

// ---------------------------------------------------------------------------
// Kernel 3: final deterministic loss reduction
// ---------------------------------------------------------------------------
__global__ void vq_loss_kernel(float* __restrict__ loss_out) {
    __shared__ float s[256];
    int tid = threadIdx.x;
    s[tid] = g_partial[tid] + g_partial[tid + 256];
    __syncthreads();
#pragma unroll
    for (int off = 128; off; off >>= 1) {
        if (tid < off) s[tid] += s[tid + off];
        __syncthreads();
    }
    if (tid == 0) loss_out[0] = (1.f + BETA) * s[0] / (float)NTOK;
}

// ---------------------------------------------------------------------------
extern "C" void kernel_launch(void* const* d_in, const int* in_sizes, int n_in,
                              void* d_out, int out_size) {
    const float* z = (const float*)d_in[0];   // [16,4096,128]
    const float* E = (const float*)d_in[1];   // [1024,128]
    float* out = (float*)d_out;

    float* zq   = out + OFF_ZQ;
    float* sim  = out + OFF_SIM;
    float* ids  = out + OFF_IDS;
    float* loss = out + OFF_LOSS;

    const int smem_bytes = (2 * DIM * PITCH + 2 * TM + 2 * TK + NTHREADS + TM) * 4;
    cudaFuncSetAttribute(vq_main_kernel,
                         cudaFuncAttributeMaxDynamicSharedMemorySize, smem_bytes);

    vq_norms_kernel<<<KC / 128, 128>>>(E);
    vq_main_kernel<<<NTOK / TM, NTHREADS, smem_bytes>>>(z, E, zq, sim, ids);
    vq_loss_kernel<<<1, 256>>>(loss);
}

// round 3
// speedup vs baseline: 1.9602x; 1.9602x over previous
#include <cuda_runtime.h>
#include <cuda_bf16.h>
#include <cstdint>

// ---------------- problem constants ----------------
#define NTOK 65536
#define DIM  128
#define KC   1024
#define TM   128            // tokens per CTA
#define TN   128            // codes per N-chunk
#define NTILES (KC / TN)    // 8
#define NTHREADS 256
#define NCTAS (NTOK / TM)   // 512
#define BETA 0.25f
#define MARGIN 4e-3f

// output layout (float32, reference return order)
#define OFF_ZQ   0
#define SZ_ZQ    (NTOK * DIM)
#define OFF_SIM  (OFF_ZQ + SZ_ZQ)              // 8388608
#define SZ_SIM   ((size_t)NTOK * KC)
#define OFF_IDS  (OFF_SIM + SZ_SIM)            // 75497472
#define OFF_LOSS (OFF_IDS + NTOK)              // 75563008

// ---------------- SMEM layout (bytes) ----------------
// bf16 tiles: 128 rows x 256 B (128 bf16)
#define SM_ZH   0
#define SM_ZL   32768
#define SM_EH0  65536
#define SM_EL0  98304
#define SM_EH1  131072
#define SM_EL1  163840
#define SM_NZ   196608      // 128 f
#define SM_RNZ  197120      // 128 f
#define SM_NE   197632      // 1024 f
#define SM_RNE  201728      // 1024 f
#define SM_RED  205824      // 256 f
#define SM_IDS  206848      // 128 i
#define SM_B1   207360      // [2][128] f
#define SM_B2   208384
#define SM_I1   209408
#define SM_I2   210432
#define SM_TOTAL 211456

__device__ float g_nsqE[KC];
__device__ float g_rnE[KC];
__device__ float g_partial[NCTAS];
__device__ __align__(16) __nv_bfloat16 g_Eh[KC * DIM];
__device__ __align__(16) __nv_bfloat16 g_El[KC * DIM];

// ---------------- PTX helpers (plain compute_103 features only) ----------
__device__ __forceinline__ uint32_t smem_u32(const void* p) {
    uint32_t a;
    asm("{ .reg .u64 t; cvta.to.shared.u64 t, %1; cvt.u32.u64 %0, t; }" : "=r"(a) : "l"(p));
    return a;
}

#define LDSM_X4(r0, r1, r2, r3, addr) \
    asm volatile("ldmatrix.sync.aligned.m8n8.x4.shared.b16 {%0,%1,%2,%3}, [%4];" \
                 : "=r"(r0), "=r"(r1), "=r"(r2), "=r"(r3) : "r"(addr))

#define MMA_BF16(d, a, b0, b1) \
    asm volatile("mma.sync.aligned.m16n8k16.row.col.f32.bf16.bf16.f32 " \
                 "{%0,%1,%2,%3}, {%4,%5,%6,%7}, {%8,%9}, {%0,%1,%2,%3};" \
                 : "+f"((d)[0]), "+f"((d)[1]), "+f"((d)[2]), "+f"((d)[3]) \
                 : "r"((a)[0]), "r"((a)[1]), "r"((a)[2]), "r"((a)[3]), \
                   "r"(b0), "r"(b1))

#define CP_ASYNC16(dst, src) \
    asm volatile("cp.async.cg.shared.global [%0], [%1], 16;" :: "r"(dst), "l"(src))
#define CP_COMMIT() asm volatile("cp.async.commit_group;" ::: "memory")
#define CP_WAIT(n)  asm volatile("cp.async.wait_group %0;" :: "n"(n) : "memory")

// swizzled byte offset: row in [0,128), 16B-chunk c in [0,16)
__device__ __forceinline__ uint32_t swz(int row, int c) {
    return (uint32_t)row * 256u + ((uint32_t)(c ^ (row & 7)) << 4);
}

// convert 8 floats -> 8 bf16 hi (uint4) and 8 bf16 lo (uint4)
__device__ __forceinline__ void split8(const float* v, uint4& hi, uint4& lo) {
    uint32_t h[4], l[4];
#pragma unroll
    for (int i = 0; i < 4; i++) {
        float x = v[2 * i], y = v[2 * i + 1];
        __nv_bfloat16 hx = __float2bfloat16(x), hy = __float2bfloat16(y);
        h[i] = (uint32_t)__bfloat16_as_ushort(hx) | ((uint32_t)__bfloat16_as_ushort(hy) << 16);
        __nv_bfloat16 lx = __float2bfloat16(x - __bfloat162float(hx));
        __nv_bfloat16 ly = __float2bfloat16(y - __bfloat162float(hy));
        l[i] = (uint32_t)__bfloat16_as_ushort(lx) | ((uint32_t)__bfloat16_as_ushort(ly) << 16);
    }
    hi = make_uint4(h[0], h[1], h[2], h[3]);
    lo = make_uint4(l[0], l[1], l[2], l[3]);
}

// top-2 merge: (b1,i1,b2,i2) <- merge with (c1,j1,c2,j2)
__device__ __forceinline__ void merge2(float& b1, int& i1, float& b2, int& i2,
                                       float c1, int j1, float c2, int j2) {
    if (c1 < b1 || (c1 == b1 && j1 < i1)) {
        float t = b1; int ti = i1;
        b1 = c1; i1 = j1;
        c1 = t;  j1 = ti;
    }
    if (c1 < b2 || (c1 == b2 && j1 < i2)) { b2 = c1; i2 = j1; }
    if (c2 < b2 || (c2 == b2 && j2 < i2)) { b2 = c2; i2 = j2; }
}

__device__ __forceinline__ float exact_pdist(const float* __restrict__ zrow,
                                             const float* __restrict__ E, int id) {
    const float4* a = reinterpret_cast<const float4*>(zrow);
    const float4* b = reinterpret_cast<const float4*>(E + (size_t)id * DIM);
    float s = 0.f;
#pragma unroll
    for (int i = 0; i < 32; i++) {
        float4 x = a[i], y = b[i];
        s = fmaf(x.x, y.x, s); s = fmaf(x.y, y.y, s);
        s = fmaf(x.z, y.z, s); s = fmaf(x.w, y.w, s);
    }
    return fmaf(-2.f, s, g_nsqE[id]);   // ne - 2*dot (nz added by caller)
}

// ---------------- kernel 1: codebook norms + bf16 hi/lo split ----------------
__global__ void vq_prep_kernel(const float* __restrict__ E) {
    int k = blockIdx.x * blockDim.x + threadIdx.x;   // 8 x 128 = 1024 rows
    const float4* row = reinterpret_cast<const float4*>(E + (size_t)k * DIM);
    float s = 0.f;
    uint4* eh = reinterpret_cast<uint4*>(g_Eh + (size_t)k * DIM);
    uint4* el = reinterpret_cast<uint4*>(g_El + (size_t)k * DIM);
#pragma unroll
    for (int c = 0; c < 16; c++) {
        float4 v0 = row[2 * c], v1 = row[2 * c + 1];
        float v[8] = {v0.x, v0.y, v0.z, v0.w, v1.x, v1.y, v1.z, v1.w};
#pragma unroll
        for (int i = 0; i < 8; i++) s = fmaf(v[i], v[i], s);
        uint4 hi, lo;
        split8(v, hi, lo);
        eh[c] = hi;
        el[c] = lo;
    }
    g_nsqE[k] = s;
    g_rnE[k]  = rsqrtf(s);
}

// ---------------- main kernel ----------------
__global__ __launch_bounds__(NTHREADS, 1)
void vq_main_kernel(const float* __restrict__ z,
                    const float* __restrict__ E,
                    float* __restrict__ zq,
                    float* __restrict__ sim,
                    float* __restrict__ ids_out) {
    extern __shared__ char smem[];
    const uint32_t smb = smem_u32(smem);
    const int tid  = threadIdx.x;
    const int wid  = tid >> 5;
    const int lane = tid & 31;
    const int wr   = wid & 3;          // token group (0..3) -> tokens wr*32..+31
    const int wc   = wid >> 2;         // col half (0..1)    -> cols wc*64..+63
    const int base = blockIdx.x * TM;

    float* s_nz  = reinterpret_cast<float*>(smem + SM_NZ);
    float* s_rnz = reinterpret_cast<float*>(smem + SM_RNZ);
    float* s_ne  = reinterpret_cast<float*>(smem + SM_NE);
    float* s_rne = reinterpret_cast<float*>(smem + SM_RNE);
    float* s_red = reinterpret_cast<float*>(smem + SM_RED);
    int*   s_ids = reinterpret_cast<int*>(smem + SM_IDS);
    float* s_b1  = reinterpret_cast<float*>(smem + SM_B1);
    float* s_b2  = reinterpret_cast<float*>(smem + SM_B2);
    int*   s_i1  = reinterpret_cast<int*>(smem + SM_I1);
    int*   s_i2  = reinterpret_cast<int*>(smem + SM_I2);

    const uint32_t ebuf_h[2] = {smb + SM_EH0, smb + SM_EH1};
    const uint32_t ebuf_l[2] = {smb + SM_EL0, smb + SM_EL1};

    // ---- issue E chunk 0 (cp.async) ----
    {
#pragma unroll
        for (int it = 0; it < 16; it++) {
            int idx = tid + it * NTHREADS;           // 0..4095
            int arr = idx >> 11;                     // 0 = hi, 1 = lo
            int rem = idx & 2047;
            int r = rem >> 4, c = rem & 15;
            const __nv_bfloat16* src = (arr ? g_El : g_Eh) + (size_t)r * DIM + c * 8;
            uint32_t dst = (arr ? ebuf_l[0] : ebuf_h[0]) + swz(r, c);
            CP_ASYNC16(dst, src);
        }
        CP_COMMIT();
    }

    // ---- z tile: convert to bf16 hi/lo (swizzled) + per-token norms ----
    {
        int t = tid >> 1, half = tid & 1;
        const float4* p = reinterpret_cast<const float4*>(z + (size_t)(base + t) * DIM + half * 64);
        float nsq = 0.f;
#pragma unroll
        for (int i = 0; i < 8; i++) {
            float4 v0 = p[2 * i], v1 = p[2 * i + 1];
            float v[8] = {v0.x, v0.y, v0.z, v0.w, v1.x, v1.y, v1.z, v1.w};
#pragma unroll
            for (int e = 0; e < 8; e++) nsq = fmaf(v[e], v[e], nsq);
            uint4 hi, lo;
            split8(v, hi, lo);
            int c = half * 8 + i;
            *reinterpret_cast<uint4*>(smem + SM_ZH + swz(t, c)) = hi;
            *reinterpret_cast<uint4*>(smem + SM_ZL + swz(t, c)) = lo;
        }
        nsq += __shfl_xor_sync(0xffffffffu, nsq, 1);
        if (!half) { s_nz[t] = nsq; s_rnz[t] = rsqrtf(nsq); }
    }
    for (int i = tid; i < KC; i += NTHREADS) {
        s_ne[i]  = g_nsqE[i];
        s_rne[i] = g_rnE[i];
    }
    __syncthreads();

    // ---- per-thread ldmatrix address components ----
    // A (x4): lane = 8*t + i;  row = tb + (t&1)*8 + i;  chunk = ks*2 + (t>>1)
    const int la_i = lane & 7;
    const int la_t = lane >> 3;
    const int rowA0 = wr * 32 + (la_t & 1) * 8 + la_i;        // mi = 0
    const int rowA1 = rowA0 + 16;                             // mi = 1
    const int cbitA = la_t >> 1;
    // B (x4, pair p): row = wc*64 + p*16 + (t>>1)*8 + i; chunk = ks*2 + (t&1)
    const int rowB_base = wc * 64 + (la_t >> 1) * 8 + la_i;
    const int cbitB = la_t & 1;

    // epilogue identity
    const int g = lane >> 2;       // row-in-tile group
    const int q = lane & 3;        // col quad
    int   tokid[4];
    float rnzv[4];
#pragma unroll
    for (int mi = 0; mi < 2; mi++)
#pragma unroll
        for (int rh = 0; rh < 2; rh++) {
            int t = wr * 32 + mi * 16 + rh * 8 + g;
            tokid[mi * 2 + rh] = t;
            rnzv[mi * 2 + rh]  = s_rnz[t];
        }

    float bd1[4], bd2[4];
    int   bi1[4], bi2[4];
#pragma unroll
    for (int r = 0; r < 4; r++) { bd1[r] = 3.4e38f; bd2[r] = 3.4e38f; bi1[r] = 0; bi2[r] = 0; }

    // ---- main loop over 8 N-chunks ----
    for (int nt = 0; nt < NTILES; nt++) {
        const int buf = nt & 1;

        // issue E chunk nt+1 into the other buffer
        if (nt + 1 < NTILES) {
            const int kb = (nt + 1) * TN;
#pragma unroll
            for (int it = 0; it < 16; it++) {
                int idx = tid + it * NTHREADS;
                int arr = idx >> 11;
                int rem = idx & 2047;
                int r = rem >> 4, c = rem & 15;
                const __nv_bfloat16* src = (arr ? g_El : g_Eh) + (size_t)(kb + r) * DIM + c * 8;
                uint32_t dst = (arr ? ebuf_l[buf ^ 1] : ebuf_h[buf ^ 1]) + swz(r, c);
                CP_ASYNC16(dst, src);
            }
            CP_COMMIT();
            CP_WAIT(1);
        } else {
            CP_WAIT(0);
        }
        __syncthreads();

        // ---- GEMM: 8 k-steps, 3 passes (hh, hl, lh) ----
        float acc[2][8][4];
#pragma unroll
        for (int mi = 0; mi < 2; mi++)
#pragma unroll
            for (int ni = 0; ni < 8; ni++)
#pragma unroll
                for (int e = 0; e < 4; e++) acc[mi][ni][e] = 0.f;

        const uint32_t zh = smb + SM_ZH, zl = smb + SM_ZL;
        const uint32_t eh = ebuf_h[buf], el = ebuf_l[buf];

#pragma unroll 1
        for (int ks = 0; ks < 8; ks++) {
            uint32_t ah[2][4], al[2][4];
            {
                uint32_t cA = (uint32_t)(ks * 2 + cbitA);
                uint32_t offA0 = (uint32_t)rowA0 * 256u + ((cA ^ (uint32_t)(rowA0 & 7)) << 4);
                uint32_t offA1 = (uint32_t)rowA1 * 256u + ((cA ^ (uint32_t)(rowA1 & 7)) << 4);
                LDSM_X4(ah[0][0], ah[0][1], ah[0][2], ah[0][3], zh + offA0);
                LDSM_X4(ah[1][0], ah[1][1], ah[1][2], ah[1][3], zh + offA1);
                LDSM_X4(al[0][0], al[0][1], al[0][2], al[0][3], zl + offA0);
                LDSM_X4(al[1][0], al[1][1], al[1][2], al[1][3], zl + offA1);
            }
            uint32_t bh[4][4], bl[4][4];
#pragma unroll
            for (int p = 0; p < 4; p++) {
                int rB = rowB_base + p * 16;
                uint32_t cB = (uint32_t)(ks * 2 + cbitB);
                uint32_t offB = (uint32_t)rB * 256u + ((cB ^ (uint32_t)(rB & 7)) << 4);
                LDSM_X4(bh[p][0], bh[p][1], bh[p][2], bh[p][3], eh + offB);
                LDSM_X4(bl[p][0], bl[p][1], bl[p][2], bl[p][3], el + offB);
            }
#pragma unroll
            for (int mi = 0; mi < 2; mi++)
#pragma unroll
                for (int ni = 0; ni < 8; ni++) {
                    uint32_t b0h = bh[ni >> 1][(ni & 1) * 2], b1h = bh[ni >> 1][(ni & 1) * 2 + 1];
                    uint32_t b0l = bl[ni >> 1][(ni & 1) * 2], b1l = bl[ni >> 1][(ni & 1) * 2 + 1];
                    MMA_BF16(acc[mi][ni], ah[mi], b0h, b1h);
                    MMA_BF16(acc[mi][ni], ah[mi], b0l, b1l);
                    MMA_BF16(acc[mi][ni], al[mi], b0h, b1h);
                }
        }

        // ---- epilogue: similarity + argmin ----
#pragma unroll
        for (int mi = 0; mi < 2; mi++)
#pragma unroll
            for (int ni = 0; ni < 8; ni++) {
                const float* a = acc[mi][ni];
                const int k = nt * TN + wc * 64 + ni * 8 + q * 2;
                const float ne0 = s_ne[k],  ne1 = s_ne[k + 1];
                const float rn0 = s_rne[k], rn1 = s_rne[k + 1];

                // row rh = 0 (regs 0,1), rh = 1 (regs 2,3)
                const int r0 = mi * 2 + 0, r1 = mi * 2 + 1;
                float d;
                d = fmaf(-2.f, a[0], ne0);
                if (d < bd1[r0]) { bd2[r0] = bd1[r0]; bi2[r0] = bi1[r0]; bd1[r0] = d; bi1[r0] = k; }
                else if (d < bd2[r0]) { bd2[r0] = d; bi2[r0] = k; }
                d = fmaf(-2.f, a[1], ne1);
                if (d < bd1[r0]) { bd2[r0] = bd1[r0]; bi2[r0] = bi1[r0]; bd1[r0] = d; bi1[r0] = k + 1; }
                else if (d < bd2[r0]) { bd2[r0] = d; bi2[r0] = k + 1; }
                d = fmaf(-2.f, a[2], ne0);
                if (d < bd1[r1]) { bd2[r1] = bd1[r1]; bi2[r1] = bi1[r1]; bd1[r1] = d; bi1[r1] = k; }
                else if (d < bd2[r1]) { bd2[r1] = d; bi2[r1] = k; }
                d = fmaf(-2.f, a[3], ne1);
                if (d < bd1[r1]) { bd2[r1] = bd1[r1]; bi2[r1] = bi1[r1]; bd1[r1] = d; bi1[r1] = k + 1; }
                else if (d < bd2[r1]) { bd2[r1] = d; bi2[r1] = k + 1; }

                float2 s0 = make_float2(a[0] * rnzv[r0] * rn0, a[1] * rnzv[r0] * rn1);
                float2 s1 = make_float2(a[2] * rnzv[r1] * rn0, a[3] * rnzv[r1] * rn1);
                *reinterpret_cast<float2*>(sim + (size_t)(base + tokid[r0]) * KC + k) = s0;
                *reinterpret_cast<float2*>(sim + (size_t)(base + tokid[r1]) * KC + k) = s1;
            }

        __syncthreads();   // all warps done reading E buf before next cp.async overwrites
    }

    // ---- reduce argmin across the 4 lanes of each row group ----
#pragma unroll
    for (int r = 0; r < 4; r++) {
        float d1 = bd1[r], d2 = bd2[r];
        int   j1 = bi1[r], j2 = bi2[r];
#pragma unroll
        for (int off = 1; off <= 2; off <<= 1) {
            float o1 = __shfl_xor_sync(0xffffffffu, d1, off);
            float o2 = __shfl_xor_sync(0xffffffffu, d2, off);
            int   p1 = __shfl_xor_sync(0xffffffffu, j1, off);
            int   p2 = __shfl_xor_sync(0xffffffffu, j2, off);
            merge2(d1, j1, d2, j2, o1, p1, o2, p2);
        }
        if (q == 0) {
            int idx = wc * TM + tokid[r];
            s_b1[idx] = d1; s_b2[idx] = d2;
            s_i1[idx] = j1; s_i2[idx] = j2;
        }
    }
    __syncthreads();

    // ---- final per-token merge + margin refine + loss ----
    float lsum = 0.f;
    if (tid < TM) {
        float b1 = s_b1[tid], b2 = s_b2[tid];
        int   i1 = s_i1[tid], i2 = s_i2[tid];
        merge2(b1, i1, b2, i2, s_b1[TM + tid], s_i1[TM + tid], s_b2[TM + tid], s_i2[TM + tid]);

        const float nz = s_nz[tid];
        if (b2 - b1 < MARGIN) {
            const float* zrow = z + (size_t)(base + tid) * DIM;
            float dA = exact_pdist(zrow, E, i1);
            float dB = exact_pdist(zrow, E, i2);
            if (dB < dA || (dB == dA && i2 < i1)) { i1 = i2; dA = dB; }
            b1 = dA;
        }
        s_ids[tid] = i1;
        ids_out[base + tid] = (float)i1;
        lsum = sqrtf(fmaxf(b1 + nz, 0.f));
    }

    s_red[tid] = lsum;
    __syncthreads();
#pragma unroll
    for (int off = NTHREADS / 2; off; off >>= 1) {
        if (tid < off) s_red[tid] += s_red[tid + off];
        __syncthreads();
    }
    if (tid == 0) g_partial[blockIdx.x] = s_red[0];

    // ---- z_q gather ----
#pragma unroll
    for (int it = 0; it < (TM * DIM / 4) / NTHREADS; it++) {
        int f  = tid + it * NTHREADS;
        int t  = f >> 5;
        int c4 = (f & 31) << 2;
        int id = s_ids[t];
        float4 v = *reinterpret_cast<const float4*>(E + (size_t)id * DIM + c4);
        *reinterpret_cast<float4*>(zq + (size_t)(base + t) * DIM + c4) = v;
    }
}

// ---------------- kernel 3: loss ----------------
__global__ void vq_loss_kernel(float* __restrict__ loss_out) {
    __shared__ float s[256];
    int tid = threadIdx.x;
    s[tid] = g_partial[tid] + g_partial[tid + 256];
    __syncthreads();
#pragma unroll
    for (int off = 128; off; off >>= 1) {
        if (tid < off) s[tid] += s[tid + off];
        __syncthreads();
    }
    if (tid == 0) loss_out[0] = (1.f + BETA) * s[0] / (float)NTOK;
}

// ---------------- launcher ----------------
extern "C" void kernel_launch(void* const* d_in, const int* in_sizes, int n_in,
                              void* d_out, int out_size) {
    const float* z = (const float*)d_in[0];
    const float* E = (const float*)d_in[1];
    float* out = (float*)d_out;

    float* zq   = out + OFF_ZQ;
    float* sim  = out + OFF_SIM;
    float* ids  = out + OFF_IDS;
    float* loss = out + OFF_LOSS;

    cudaFuncSetAttribute(vq_main_kernel,
                         cudaFuncAttributeMaxDynamicSharedMemorySize, SM_TOTAL);

    vq_prep_kernel<<<KC / 128, 128>>>(E);
    vq_main_kernel<<<NCTAS, NTHREADS, SM_TOTAL>>>(z, E, zq, sim, ids);
    vq_loss_kernel<<<1, 256>>>(loss);
}